// round 16
// baseline (speedup 1.0000x reference)
#include <cuda_runtime.h>
#include <math.h>

#define BB 16
#define TT 1024
#define DD 256
#define KK 64
#define NBLK (BB * KK)
#define LOG2PI 1.8378770664093453f
#define HALF_L2PI 0.91893853320467274f
#define LN2 0.69314718055994531f

// ---- persistent device scratch (zero-initialized at module load; the
//      finalizer restores zeros so every launch sees the same state) ----
__device__ double g_acc;
__device__ int    g_done;
__device__ volatile int g_flag;
__device__ float4 g_tab[DD];          // {cc, c00, cst, b0} per dim

// Stirling correction poly: 1/(12z) - 1/(360z^3) + 1/(1260z^5)
__device__ __forceinline__ float stir(float r) {
    float r2 = r * r;
    return r * fmaf(-r2, fmaf(-r2, 7.9365079e-4f, 2.7777778e-3f), 8.3333333e-2f);
}

// direct Stirling lgamma — valid for x >= ~2.5 (abs err < ~1e-6)
__device__ __forceinline__ float lgf_s(float x) {
    float lx = __logf(x);
    float r  = __fdividef(1.0f, x);
    return fmaf(x - 0.5f, lx, -x) + HALF_L2PI + stir(r);
}

// g(x) = lgamma(x) + 0.5*log(x) = x*ln x - x + C + stir  — for x >= ~2.5
__device__ __forceinline__ float g_fn(float x) {
    float lx = __logf(x);
    float r  = __fdividef(1.0f, x);
    return fmaf(x, lx, -x) + HALF_L2PI + stir(r);
}

// shift-by-2 lgamma — valid for x >= ~0.5
__device__ __forceinline__ float lgf2(float x) {
    float z  = x + 2.0f;
    float lx = __logf(z);
    float r  = __fdividef(1.0f, z);
    float lg = fmaf(z - 0.5f, lx, -z) + HALF_L2PI + stir(r);
    return lg - __logf(x * (x + 1.0f));
}

#define PROC4(xv)                                              \
    do {                                                        \
        float u0 = __log2f((xv).x > 0.0f ? (xv).x : 1.0f);      \
        float u1 = __log2f((xv).y > 0.0f ? (xv).y : 1.0f);      \
        float u2 = __log2f((xv).z > 0.0f ? (xv).z : 1.0f);      \
        float u3 = __log2f((xv).w > 0.0f ? (xv).w : 1.0f);      \
        s10 += u0; s11 += u1; s12 += u2; s13 += u3;             \
        s20 = fmaf(u0, u0, s20); s21 = fmaf(u1, u1, s21);       \
        s22 = fmaf(u2, u2, s22); s23 = fmaf(u3, u3, s23);       \
        n10 += ((xv).x > 0.0f); n11 += ((xv).y > 0.0f);         \
        n12 += ((xv).z > 0.0f); n13 += ((xv).w > 0.0f);         \
    } while (0)

#define RED2(v)                                                \
    do { v += __shfl_xor_sync(0xffffffffu, v, 1);              \
         v += __shfl_xor_sync(0xffffffffu, v, 2); } while (0)

// ---- single fused kernel: block (b,k); 256 threads ----
// phase 1: thread = (row-group g = tid&3, column-quad c = tid>>2), float4 loads
// phase 2: butterfly-shuffle group reduction; thread = dim; table epilogue
__global__ void __launch_bounds__(DD) k_main(const float* __restrict__ X,
                                             const int* __restrict__ z,
                                             const float* __restrict__ loc,
                                             const float* __restrict__ lcg,
                                             const float* __restrict__ lsc,
                                             const float* __restrict__ spl,
                                             float* __restrict__ out) {
    int bk = blockIdx.x;
    int b  = bk >> 6;                                 // / KK
    int k  = bk & (KK - 1);
    int tid = threadIdx.x;
    int lane = tid & 31;

    // ---- unordered bucket build (suffstats are order-independent) ----
    __shared__ int tbuf[TT];                          // stores t*DD
    __shared__ int cnt_s;
    if (tid == 0) cnt_s = 0;
    __syncthreads();
    int4 zq = reinterpret_cast<const int4*>(z + b * TT)[tid];   // 4 t's per thread
    int t0 = tid * 4;
    if (zq.x == k) tbuf[atomicAdd(&cnt_s, 1)] = (t0 + 0) * DD;
    if (zq.y == k) tbuf[atomicAdd(&cnt_s, 1)] = (t0 + 1) * DD;
    if (zq.z == k) tbuf[atomicAdd(&cnt_s, 1)] = (t0 + 2) * DD;
    if (zq.w == k) tbuf[atomicAdd(&cnt_s, 1)] = (t0 + 3) * DD;
    __syncthreads();
    int cnt = cnt_s;

    // ---- block 0 publishes the per-d constant table; release protocol ----
    if (bk == 0) {
        float cc   = __expf(lcg[tid]);
        float kap0 = fmaf(2.0f, cc, 3.0f);
        float tc4  = kap0 + 1.0f;
        float c00  = tc4 * __expf(spl[tid]);
        float s0   = tc4 + c00;
        float cst  = -lgf2(cc) - g_fn(kap0) - lgf_s(c00) + lgf_s(s0);
        g_tab[tid] = make_float4(cc, c00, cst, __expf(lsc[tid]));
        __threadfence();                              // writes visible gpu-wide
        __syncthreads();                              // all 256 writes done
        if (tid == 0) atomicExch((int*)&g_flag, 1);   // release
    }

    // ---- phase 1: float4 gather + per-thread partial suffstats ----
    int g  = tid & 3;                                 // row group (low lane bits)
    int c  = tid >> 2;                                // column quad
    const float* Xb = X + (size_t)b * TT * DD + c * 4;

    float n10 = 0, n11 = 0, n12 = 0, n13 = 0;
    float s10 = 0, s11 = 0, s12 = 0, s13 = 0;
    float s20 = 0, s21 = 0, s22 = 0, s23 = 0;

    int i = g;
    for (; i + 4 < cnt; i += 8) {                     // 2 rows in flight
        float4 xa = *reinterpret_cast<const float4*>(Xb + tbuf[i]);
        float4 xb = *reinterpret_cast<const float4*>(Xb + tbuf[i + 4]);
        PROC4(xa); PROC4(xb);
    }
    if (i < cnt) {
        float4 xa = *reinterpret_cast<const float4*>(Xb + tbuf[i]);
        PROC4(xa);
    }

    // ---- cross-group reduction: butterfly over lane bits 0,1 (g = tid&3) ----
    RED2(n10); RED2(n11); RED2(n12); RED2(n13);
    RED2(s10); RED2(s11); RED2(s12); RED2(s13);
    RED2(s20); RED2(s21); RED2(s22); RED2(s23);

    // thread tid owns dim tid = 4c + j with j = tid&3 = g: select j-th stat
    float n1 = (g == 0) ? n10 : (g == 1) ? n11 : (g == 2) ? n12 : n13;
    float S1 = (g == 0) ? s10 : (g == 1) ? s11 : (g == 2) ? s12 : s13;
    float S2 = (g == 0) ? s20 : (g == 1) ? s21 : (g == 2) ? s22 : s23;
    S1 *= LN2; S2 *= LN2 * LN2;                       // log2 -> natural log

    // ---- acquire the table: spin, THEN fence (orders table reads after) ----
    if (bk != 0) {
        while (g_flag == 0) {}
        __threadfence();                              // acquire
    }
    float4 tb = g_tab[tid];

    // ---- epilogue from sufficient statistics (verified math) ----
    float cc   = tb.x;
    float c00  = tb.y;
    float cst  = tb.z;
    float b0   = tb.w;
    float m0   = loc[tid];
    float lb0  = lsc[tid];
    float kap0 = fmaf(2.0f, cc, 3.0f);
    float tc4  = kap0 + 1.0f;
    float s0   = tc4 + c00;
    float cntf = (float)cnt;
    float n0f  = cntf - n1;

    float rn   = (n1 > 0.0f) ? __fdividef(1.0f, n1) : 0.0f;
    float tbar = S1 * rn;
    float dm   = tbar - m0;
    float bb   = b0 + 0.5f * (S2 - S1 * tbar)
               + __fdividef(kap0 * n1 * dm * dm, 2.0f * (kap0 + n1));

    float acc = -S1;                                  // Jacobian
    acc -= 0.5f * n1 * lb0 + fmaf(0.5f, n1, cc) * (__logf(bb) - lb0);
    acc += cst
         + lgf2(fmaf(0.5f, n1, cc))
         + g_fn(kap0 + n1)
         - 0.5f * n1 * LOG2PI;
    acc += lgf_s(c00 + n0f) - lgf_s(s0 + cntf);

    // CRP numerator for this (b,k): lgamma(cnt)  (ALPHA=1)
    if (tid == 0 && cnt > 0) acc += lgf2(cntf);

    // ---- block reduce (256 threads) ----
#pragma unroll
    for (int o = 16; o; o >>= 1) acc += __shfl_xor_sync(0xffffffffu, acc, o);
    __shared__ float wsum[DD / 32];
    int wid = tid >> 5;
    if (lane == 0) wsum[wid] = acc;
    __syncthreads();
    if (tid == 0) {
        float s = 0.0f;
#pragma unroll
        for (int w = 0; w < DD / 32; ++w) s += wsum[w];
        atomicAdd(&g_acc, (double)s);
        __threadfence();
        int prev = atomicAdd(&g_done, 1);
        if (prev == NBLK - 1) {
            double tot = atomicAdd(&g_acc, 0.0);      // read-after-fence
            tot -= (double)BB * (double)lgf_s((float)(TT + 1));  // CRP denominator
            out[0] = (float)(-tot / (double)BB);
            g_acc  = 0.0;                             // restore for next replay
            g_done = 0;
            g_flag = 0;
        }
    }
}

extern "C" void kernel_launch(void* const* d_in, const int* in_sizes, int n_in,
                              void* d_out, int out_size) {
    const float* X   = (const float*)d_in[0];
    const int*   z   = (const int*)d_in[1];
    const float* loc = (const float*)d_in[2];
    const float* lcg = (const float*)d_in[3];
    const float* lsc = (const float*)d_in[4];
    const float* spl = (const float*)d_in[5];

    k_main<<<NBLK, DD>>>(X, z, loc, lcg, lsc, spl, (float*)d_out);
}

// round 17
// speedup vs baseline: 1.1855x; 1.1855x over previous
#include <cuda_runtime.h>
#include <math.h>

#define BB 16
#define TT 1024
#define DD 256
#define KK 64
#define NBLK (BB * KK)
#define LOG2PI 1.8378770664093453f
#define HALF_L2PI 0.91893853320467274f
#define LN2 0.69314718055994531f

// ---- persistent device scratch (zero-initialized at module load; the
//      finalizer restores zeros so every launch sees the same state) ----
__device__ double g_acc;
__device__ int    g_done;
__device__ float4 g_tab[DD];          // {cc, c00, cst, b0} per dim

// Stirling correction poly: 1/(12z) - 1/(360z^3) + 1/(1260z^5)
__device__ __forceinline__ float stir(float r) {
    float r2 = r * r;
    return r * fmaf(-r2, fmaf(-r2, 7.9365079e-4f, 2.7777778e-3f), 8.3333333e-2f);
}

// direct Stirling lgamma — valid for x >= ~2.5 (abs err < ~1e-6)
__device__ __forceinline__ float lgf_s(float x) {
    float lx = __logf(x);
    float r  = __fdividef(1.0f, x);
    return fmaf(x - 0.5f, lx, -x) + HALF_L2PI + stir(r);
}

// g(x) = lgamma(x) + 0.5*log(x) = x*ln x - x + C + stir  — for x >= ~2.5
__device__ __forceinline__ float g_fn(float x) {
    float lx = __logf(x);
    float r  = __fdividef(1.0f, x);
    return fmaf(x, lx, -x) + HALF_L2PI + stir(r);
}

// shift-by-2 lgamma — valid for x >= ~0.5
__device__ __forceinline__ float lgf2(float x) {
    float z  = x + 2.0f;
    float lx = __logf(z);
    float r  = __fdividef(1.0f, z);
    float lg = fmaf(z - 0.5f, lx, -z) + HALF_L2PI + stir(r);
    return lg - __logf(x * (x + 1.0f));
}

#define PROC4(xv)                                              \
    do {                                                        \
        float u0 = __log2f((xv).x > 0.0f ? (xv).x : 1.0f);      \
        float u1 = __log2f((xv).y > 0.0f ? (xv).y : 1.0f);      \
        float u2 = __log2f((xv).z > 0.0f ? (xv).z : 1.0f);      \
        float u3 = __log2f((xv).w > 0.0f ? (xv).w : 1.0f);      \
        s10 += u0; s11 += u1; s12 += u2; s13 += u3;             \
        s20 = fmaf(u0, u0, s20); s21 = fmaf(u1, u1, s21);       \
        s22 = fmaf(u2, u2, s22); s23 = fmaf(u3, u3, s23);       \
        n10 += ((xv).x > 0.0f); n11 += ((xv).y > 0.0f);         \
        n12 += ((xv).z > 0.0f); n13 += ((xv).w > 0.0f);         \
    } while (0)

// ---- kernel 0: per-d constant table (1 block, 256 threads) ----
__global__ void k_tab(const float* __restrict__ lcg,
                      const float* __restrict__ lsc,
                      const float* __restrict__ spl) {
    int d = threadIdx.x;
    float cc   = __expf(lcg[d]);
    float kap0 = fmaf(2.0f, cc, 3.0f);
    float tc4  = kap0 + 1.0f;
    float c00  = tc4 * __expf(spl[d]);
    float s0   = tc4 + c00;
    float cst  = -lgf2(cc) - g_fn(kap0) - lgf_s(c00) + lgf_s(s0);
    g_tab[d] = make_float4(cc, c00, cst, __expf(lsc[d]));
}

// ---- kernel 1: block (b,k); 256 threads (round-10 proven body) ----
// phase 1: thread = (row-group g = tid>>6, column-quad c = tid&63), float4 loads
// phase 2: reduce groups via smem; thread = dim; table epilogue
__global__ void __launch_bounds__(DD) k_main(const float* __restrict__ X,
                                             const int* __restrict__ z,
                                             const float* __restrict__ loc,
                                             const float* __restrict__ lsc,
                                             float* __restrict__ out) {
    int bk = blockIdx.x;
    int b  = bk >> 6;                                 // / KK
    int k  = bk & (KK - 1);
    int tid = threadIdx.x;

    // ---- unordered bucket build (suffstats are order-independent) ----
    __shared__ int tbuf[TT];                          // stores t*DD
    __shared__ int cnt_s;
    if (tid == 0) cnt_s = 0;
    __syncthreads();
    int4 zq = reinterpret_cast<const int4*>(z + b * TT)[tid];   // 4 t's per thread
    int t0 = tid * 4;
    if (zq.x == k) tbuf[atomicAdd(&cnt_s, 1)] = (t0 + 0) * DD;
    if (zq.y == k) tbuf[atomicAdd(&cnt_s, 1)] = (t0 + 1) * DD;
    if (zq.z == k) tbuf[atomicAdd(&cnt_s, 1)] = (t0 + 2) * DD;
    if (zq.w == k) tbuf[atomicAdd(&cnt_s, 1)] = (t0 + 3) * DD;
    __syncthreads();
    int cnt = cnt_s;

    // ---- phase 1: float4 gather + per-thread partial suffstats ----
    int g  = tid >> 6;                                // row group 0..3
    int c  = tid & 63;                                // column quad
    const float* Xb = X + (size_t)b * TT * DD + c * 4;

    float n10 = 0, n11 = 0, n12 = 0, n13 = 0;
    float s10 = 0, s11 = 0, s12 = 0, s13 = 0;
    float s20 = 0, s21 = 0, s22 = 0, s23 = 0;

    int i = g;
    for (; i + 4 < cnt; i += 8) {                     // 2 rows in flight
        float4 xa = *reinterpret_cast<const float4*>(Xb + tbuf[i]);
        float4 xb = *reinterpret_cast<const float4*>(Xb + tbuf[i + 4]);
        PROC4(xa); PROC4(xb);
    }
    if (i < cnt) {
        float4 xa = *reinterpret_cast<const float4*>(Xb + tbuf[i]);
        PROC4(xa);
    }

    // ---- cross-group reduction via padded smem stage (deterministic) ----
    __shared__ float stg[4 * 64 * 13];                // pad 12->13: conflict-free
    float* my = stg + (g * 64 + c) * 13;
    my[0] = n10; my[1] = n11; my[2]  = n12; my[3]  = n13;
    my[4] = s10; my[5] = s11; my[6]  = s12; my[7]  = s13;
    my[8] = s20; my[9] = s21; my[10] = s22; my[11] = s23;
    __syncthreads();

    int dc = tid >> 2, dj = tid & 3;                  // dim = 4*dc + dj = tid
    float n1 = 0.0f, S1 = 0.0f, S2 = 0.0f;
#pragma unroll
    for (int gg = 0; gg < 4; ++gg) {
        const float* p = stg + (gg * 64 + dc) * 13;
        n1 += p[dj]; S1 += p[4 + dj]; S2 += p[8 + dj];
    }
    S1 *= LN2; S2 *= LN2 * LN2;                       // log2 -> natural log

    // ---- epilogue from sufficient statistics + constant table ----
    float4 tb  = g_tab[tid];                          // stream-ordered: valid
    float cc   = tb.x;
    float c00  = tb.y;
    float cst  = tb.z;
    float b0   = tb.w;
    float m0   = __ldg(loc + tid);
    float lb0  = __ldg(lsc + tid);
    float kap0 = fmaf(2.0f, cc, 3.0f);
    float tc4  = kap0 + 1.0f;
    float s0   = tc4 + c00;
    float cntf = (float)cnt;
    float n0f  = cntf - n1;

    float rn   = (n1 > 0.0f) ? __fdividef(1.0f, n1) : 0.0f;
    float tbar = S1 * rn;
    float dm   = tbar - m0;
    float bb   = b0 + 0.5f * (S2 - S1 * tbar)
               + __fdividef(kap0 * n1 * dm * dm, 2.0f * (kap0 + n1));

    float acc = -S1;                                  // Jacobian
    acc -= 0.5f * n1 * lb0 + fmaf(0.5f, n1, cc) * (__logf(bb) - lb0);
    acc += cst
         + lgf2(fmaf(0.5f, n1, cc))
         + g_fn(kap0 + n1)
         - 0.5f * n1 * LOG2PI;
    acc += lgf_s(c00 + n0f) - lgf_s(s0 + cntf);

    // CRP numerator for this (b,k): lgamma(cnt)  (ALPHA=1)
    if (tid == 0 && cnt > 0) acc += lgf2(cntf);

    // ---- block reduce (256 threads) ----
#pragma unroll
    for (int o = 16; o; o >>= 1) acc += __shfl_xor_sync(0xffffffffu, acc, o);
    __shared__ float wsum[DD / 32];
    int lane = tid & 31, wid = tid >> 5;
    if (lane == 0) wsum[wid] = acc;
    __syncthreads();
    if (tid == 0) {
        float s = 0.0f;
#pragma unroll
        for (int w = 0; w < DD / 32; ++w) s += wsum[w];
        atomicAdd(&g_acc, (double)s);
        __threadfence();
        int prev = atomicAdd(&g_done, 1);
        if (prev == NBLK - 1) {
            double tot = atomicAdd(&g_acc, 0.0);      // read-after-fence
            tot -= (double)BB * (double)lgf_s((float)(TT + 1));  // CRP denominator
            out[0] = (float)(-tot / (double)BB);
            g_acc  = 0.0;                             // restore for next replay
            g_done = 0;
        }
    }
}

extern "C" void kernel_launch(void* const* d_in, const int* in_sizes, int n_in,
                              void* d_out, int out_size) {
    const float* X   = (const float*)d_in[0];
    const int*   z   = (const int*)d_in[1];
    const float* loc = (const float*)d_in[2];
    const float* lcg = (const float*)d_in[3];
    const float* lsc = (const float*)d_in[4];
    const float* spl = (const float*)d_in[5];

    k_tab<<<1, DD>>>(lcg, lsc, spl);
    k_main<<<NBLK, DD>>>(X, z, loc, lsc, (float*)d_out);
}